// round 3
// baseline (speedup 1.0000x reference)
#include <cuda_runtime.h>
#include <cstddef>
#include <cstdint>

#define E_BONDS   200000
#define NATOMS    100000
#define HID       128
#define MAX_NB    15
#define BFD       23      // ATOM_FDIM + BOND_FDIM
#define AFD       18      // ATOM_FDIM
#define AIN       146     // AFD + HID
#define AINP      148     // padded to multiple of 4
#define NMOLS     2000
#define NPASS     5       // DEPTH - 1

#define NEI_S     132     // row stride (floats) for nei tile: 132*4B, 16B-aligned

// ---- scratch (device globals: alloc-free, graph-capturable) ----
__device__ float g_binput[(size_t)E_BONDS * HID];
__device__ float g_msgA  [(size_t)E_BONDS * HID];
__device__ float g_msgB  [(size_t)E_BONDS * HID];
__device__ float g_atomh [(size_t)NATOMS  * HID];

// ---- packed f32x2 helpers (sm_103a) ----
__device__ __forceinline__ unsigned long long pack2(float lo, float hi) {
    unsigned long long r;
    asm("mov.b64 %0, {%1, %2};" : "=l"(r) : "f"(lo), "f"(hi));
    return r;
}
__device__ __forceinline__ void unpack2(unsigned long long v, float& lo, float& hi) {
    asm("mov.b64 {%0, %1}, %2;" : "=f"(lo), "=f"(hi) : "l"(v));
}
__device__ __forceinline__ void ffma2(unsigned long long& d,
                                      unsigned long long a, unsigned long long b) {
    asm("fma.rn.f32x2 %0, %1, %2, %0;" : "+l"(d) : "l"(a), "l"(b));
}

// ============================================================
// Kernel 1: binput = fbonds @ W_i ; msgA = relu(binput)
// ============================================================
__global__ __launch_bounds__(256)
void k_binput(const float* __restrict__ fbonds,
              const float* __restrict__ W_i)
{
    __shared__ float Wsh[BFD * HID];
    int t = threadIdx.x;
    for (int i = t; i < BFD * HID; i += 256) Wsh[i] = W_i[i];
    __syncthreads();

    int c4 = t & 31, w = t >> 5;
    int gw = blockIdx.x * 8 + w;
    const int nwarps = gridDim.x * 8;

    for (int row = gw; row < E_BONDS; row += nwarps) {
        const float* fr = fbonds + (size_t)row * BFD;
        float4 acc = make_float4(0.f, 0.f, 0.f, 0.f);
        #pragma unroll
        for (int k = 0; k < BFD; k++) {
            float f = __ldg(fr + k);
            float4 wv = *(const float4*)&Wsh[k * HID + c4 * 4];
            acc.x += f * wv.x; acc.y += f * wv.y;
            acc.z += f * wv.z; acc.w += f * wv.w;
        }
        size_t o = (size_t)row * HID + c4 * 4;
        *(float4*)&g_binput[o] = acc;
        float4 rr;
        rr.x = fmaxf(acc.x, 0.f); rr.y = fmaxf(acc.y, 0.f);
        rr.z = fmaxf(acc.z, 0.f); rr.w = fmaxf(acc.w, 0.f);
        *(float4*)&g_msgA[o] = rr;
    }
}

// ============================================================
// Kernel 2: message pass, 64-row tiles, 256 thr, 2 blk/SM.
// nei stored ROW-major [64][NEI_S]: gather STS.128 conflict-free,
// GEMM reads nei via LDS.128 broadcast (1 per row per 4 k).
// Thread tile: 8 rows x 4 cols, packed f32x2 FMA.
// smem: Wsh 64KB + nei 33KB + idx 4KB = 101KB
// ============================================================
__global__ __launch_bounds__(256, 2)
void k_msgpass(const int* __restrict__ bgraph,
               const float* __restrict__ W_h,
               int flag)  // 0: A->B, 1: B->A
{
    extern __shared__ float smem[];
    float* Wsh = smem;                        // [128][128]
    float* nei = smem + HID * HID;            // [64][NEI_S]
    int*   idx = (int*)(nei + 64 * NEI_S);    // [64][16]

    const float* __restrict__ msg_in  = flag ? g_msgB : g_msgA;
    float*       __restrict__ msg_out = flag ? g_msgA : g_msgB;

    const int t  = threadIdx.x;
    const int c4 = t & 31;      // lane -> 4 cols
    const int wg = t >> 5;      // warp -> 8 rows

    for (int i = t; i < (HID * HID) / 4; i += 256)
        ((float4*)Wsh)[i] = ((const float4*)W_h)[i];
    __syncthreads();

    const int ntiles = E_BONDS / 64;   // 3125
    for (int tile = blockIdx.x; tile < ntiles; tile += gridDim.x) {
        const int base = tile * 64;
        const int r0   = wg * 8;

        // stage neighbor indices
        for (int i = t; i < 64 * MAX_NB; i += 256) {
            int r = i / MAX_NB, nb = i - r * MAX_NB;
            idx[r * 16 + nb] = __ldg(bgraph + (size_t)(base + r) * MAX_NB + nb);
        }
        __syncthreads();

        // gather-sum: warp wg -> rows r0..r0+7, lane c4 -> 16B slice
        #pragma unroll
        for (int i = 0; i < 8; i++) {
            int r = r0 + i;
            float sx = 0.f, sy = 0.f, sz = 0.f, sw = 0.f;
            #pragma unroll
            for (int nb = 0; nb < MAX_NB; nb++) {
                int e = idx[r * 16 + nb];
                float4 v = *(const float4*)(msg_in + (size_t)e * HID + c4 * 4);
                sx += v.x; sy += v.y; sz += v.z; sw += v.w;
            }
            float4 s = make_float4(sx, sy, sz, sw);
            *(float4*)&nei[r * NEI_S + c4 * 4] = s;   // conflict-free STS.128
        }
        __syncthreads();

        // GEMM + bias + relu: thread = rows r0..r0+7, cols 4c4..4c4+3
        {
            unsigned long long acc[8][2];
            #pragma unroll
            for (int i = 0; i < 8; i++) {
                float4 b = *(const float4*)&g_binput[(size_t)(base + r0 + i) * HID + c4 * 4];
                acc[i][0] = pack2(b.x, b.y);
                acc[i][1] = pack2(b.z, b.w);
            }
            #pragma unroll 2
            for (int k0 = 0; k0 < HID; k0 += 4) {
                ulonglong2 w0 = *(const ulonglong2*)&Wsh[(k0 + 0) * HID + c4 * 4];
                ulonglong2 w1 = *(const ulonglong2*)&Wsh[(k0 + 1) * HID + c4 * 4];
                ulonglong2 w2 = *(const ulonglong2*)&Wsh[(k0 + 2) * HID + c4 * 4];
                ulonglong2 w3 = *(const ulonglong2*)&Wsh[(k0 + 3) * HID + c4 * 4];
                #pragma unroll
                for (int i = 0; i < 8; i++) {
                    float4 nv = *(const float4*)&nei[(r0 + i) * NEI_S + k0]; // broadcast
                    unsigned long long p;
                    p = pack2(nv.x, nv.x); ffma2(acc[i][0], p, w0.x); ffma2(acc[i][1], p, w0.y);
                    p = pack2(nv.y, nv.y); ffma2(acc[i][0], p, w1.x); ffma2(acc[i][1], p, w1.y);
                    p = pack2(nv.z, nv.z); ffma2(acc[i][0], p, w2.x); ffma2(acc[i][1], p, w2.y);
                    p = pack2(nv.w, nv.w); ffma2(acc[i][0], p, w3.x); ffma2(acc[i][1], p, w3.y);
                }
            }
            #pragma unroll
            for (int i = 0; i < 8; i++) {
                float4 o;
                unpack2(acc[i][0], o.x, o.y);
                unpack2(acc[i][1], o.z, o.w);
                o.x = fmaxf(o.x, 0.f); o.y = fmaxf(o.y, 0.f);
                o.z = fmaxf(o.z, 0.f); o.w = fmaxf(o.w, 0.f);
                *(float4*)&msg_out[(size_t)(base + r0 + i) * HID + c4 * 4] = o;
            }
        }
        __syncthreads();
    }
}

// ============================================================
// Kernel 3: atom readout. 32-row tiles, row-major ain[32][AINP],
// K padded 146->148 (zeroed W rows + zeroed ain tail cols).
// ============================================================
__global__ __launch_bounds__(256, 2)
void k_atomh(const float* __restrict__ fatoms,
             const int*   __restrict__ agraph,
             const float* __restrict__ W_o,
             const float* __restrict__ b_o)
{
    extern __shared__ float smem[];
    float* Wsh = smem;                        // [148][128]
    float* ain = smem + AINP * HID;           // [32][AINP]
    int*   idx = (int*)(ain + 32 * AINP);     // [32][16]
    __shared__ float bsh[HID];

    const int t  = threadIdx.x;
    const int c4 = t & 31;
    const int wg = t >> 5;

    for (int i = t; i < (AIN * HID) / 4; i += 256)
        ((float4*)Wsh)[i] = ((const float4*)W_o)[i];
    for (int i = t + AIN * HID; i < AINP * HID; i += 256)
        Wsh[i] = 0.f;                          // zero pad rows 146..147
    if (t < HID) bsh[t] = b_o[t];
    __syncthreads();

    const int ntiles = NATOMS / 32;
    for (int tile = blockIdx.x; tile < ntiles; tile += gridDim.x) {
        const int base = tile * 32;
        const int r0   = wg * 4;

        for (int i = t; i < 32 * MAX_NB; i += 256) {
            int r = i / MAX_NB, nb = i - r * MAX_NB;
            idx[r * 16 + nb] = __ldg(agraph + (size_t)(base + r) * MAX_NB + nb);
        }
        // fatoms cols (k = 0..17) + zero tail (146,147)
        for (int i = t; i < AFD * 32; i += 256) {
            int r = i >> 5, k = 0;
            // i = r*... use simple mapping: r = i / AFD? keep k-major fill:
            k = i % AFD; r = i / AFD;
            ain[r * AINP + k] = __ldg(fatoms + (size_t)(base + r) * AFD + k);
        }
        if (t < 64) {
            int r = t >> 1, k = AIN + (t & 1);
            ain[r * AINP + k] = 0.f;
        }
        __syncthreads();

        // gather cols k = 18..145: warp wg -> rows 4wg..4wg+3
        #pragma unroll
        for (int i = 0; i < 4; i++) {
            int r = r0 + i;
            float sx = 0.f, sy = 0.f, sz = 0.f, sw = 0.f;
            #pragma unroll
            for (int nb = 0; nb < MAX_NB; nb++) {
                int e = idx[r * 16 + nb];
                float4 v = *(const float4*)(g_msgB + (size_t)e * HID + c4 * 4);
                sx += v.x; sy += v.y; sz += v.z; sw += v.w;
            }
            // store 4 scalars at cols AFD+4c4.. (AFD=18, not 16B aligned -> scalar)
            float* dst = &ain[r * AINP + AFD + c4 * 4];
            dst[0] = sx; dst[1] = sy; dst[2] = sz; dst[3] = sw;
        }
        __syncthreads();

        {
            unsigned long long acc[4][2];
            unsigned long long b01 = pack2(bsh[c4 * 4 + 0], bsh[c4 * 4 + 1]);
            unsigned long long b23 = pack2(bsh[c4 * 4 + 2], bsh[c4 * 4 + 3]);
            #pragma unroll
            for (int i = 0; i < 4; i++) { acc[i][0] = b01; acc[i][1] = b23; }
            #pragma unroll 2
            for (int k0 = 0; k0 < AINP; k0 += 4) {
                ulonglong2 w0 = *(const ulonglong2*)&Wsh[(k0 + 0) * HID + c4 * 4];
                ulonglong2 w1 = *(const ulonglong2*)&Wsh[(k0 + 1) * HID + c4 * 4];
                ulonglong2 w2 = *(const ulonglong2*)&Wsh[(k0 + 2) * HID + c4 * 4];
                ulonglong2 w3 = *(const ulonglong2*)&Wsh[(k0 + 3) * HID + c4 * 4];
                #pragma unroll
                for (int i = 0; i < 4; i++) {
                    float4 nv = *(const float4*)&ain[(r0 + i) * AINP + k0];
                    unsigned long long p;
                    p = pack2(nv.x, nv.x); ffma2(acc[i][0], p, w0.x); ffma2(acc[i][1], p, w0.y);
                    p = pack2(nv.y, nv.y); ffma2(acc[i][0], p, w1.x); ffma2(acc[i][1], p, w1.y);
                    p = pack2(nv.z, nv.z); ffma2(acc[i][0], p, w2.x); ffma2(acc[i][1], p, w2.y);
                    p = pack2(nv.w, nv.w); ffma2(acc[i][0], p, w3.x); ffma2(acc[i][1], p, w3.y);
                }
            }
            #pragma unroll
            for (int i = 0; i < 4; i++) {
                float4 o;
                unpack2(acc[i][0], o.x, o.y);
                unpack2(acc[i][1], o.z, o.w);
                o.x = fmaxf(o.x, 0.f); o.y = fmaxf(o.y, 0.f);
                o.z = fmaxf(o.z, 0.f); o.w = fmaxf(o.w, 0.f);
                *(float4*)&g_atomh[(size_t)(base + r0 + i) * HID + c4 * 4] = o;
            }
        }
        __syncthreads();
    }
}

// ============================================================
// Kernel 4: segment mean pooling.
// ============================================================
__global__ void k_pool(const int* __restrict__ scope_start,
                       const int* __restrict__ scope_len,
                       float* __restrict__ out)
{
    int m = blockIdx.x, t = threadIdx.x; // 128 threads
    int s = scope_start[m], L = scope_len[m];
    float acc = 0.f;
    for (int i = 0; i < L; i++)
        acc += g_atomh[(size_t)(s + i) * HID + t];
    out[(size_t)m * HID + t] = acc / (float)L;
}

// ============================================================
extern "C" void kernel_launch(void* const* d_in, const int* in_sizes, int n_in,
                              void* d_out, int out_size)
{
    const float* fatoms      = (const float*)d_in[0];
    const float* fbonds      = (const float*)d_in[1];
    const int*   agraph      = (const int*)  d_in[2];
    const int*   bgraph      = (const int*)  d_in[3];
    const int*   scope_start = (const int*)  d_in[4];
    const int*   scope_len   = (const int*)  d_in[5];
    const float* W_i         = (const float*)d_in[6];
    const float* W_h         = (const float*)d_in[7];
    const float* W_o         = (const float*)d_in[8];
    const float* b_o         = (const float*)d_in[9];
    float* out = (float*)d_out;

    const int SMEM2 = (HID * HID + 64 * NEI_S + 64 * 16) * 4;        // 103424
    const int SMEM3 = (AINP * HID + 32 * AINP + 32 * 16) * 4;        // 96768

    cudaFuncSetAttribute(k_msgpass, cudaFuncAttributeMaxDynamicSharedMemorySize, SMEM2);
    cudaFuncSetAttribute(k_atomh,   cudaFuncAttributeMaxDynamicSharedMemorySize, SMEM3);

    k_binput<<<1024, 256>>>(fbonds, W_i);

    for (int d = 0; d < NPASS; d++)
        k_msgpass<<<296, 256, SMEM2>>>(bgraph, W_h, d & 1);

    k_atomh<<<296, 256, SMEM3>>>(fatoms, agraph, W_o, b_o);

    k_pool<<<NMOLS, 128>>>(scope_start, scope_len, out);
}

// round 4
// speedup vs baseline: 1.1080x; 1.1080x over previous
#include <cuda_runtime.h>
#include <cstddef>
#include <cstdint>

#define E_BONDS   200000
#define NATOMS    100000
#define HID       128
#define MAX_NB    15
#define BFD       23      // ATOM_FDIM + BOND_FDIM
#define AFD       18      // ATOM_FDIM
#define AIN       146     // AFD + HID
#define AINP      148     // padded K for atomh
#define NMOLS     2000
#define NPASS     5       // DEPTH - 1

#define NEI_S     132     // nei row stride (floats): 16B-aligned, stride-132 rows
                          // put consecutive rows 4 banks apart -> conflict-free

// ---- scratch (device globals: alloc-free, graph-capturable) ----
__device__ float g_binput[(size_t)E_BONDS * HID];
__device__ float g_msgA  [(size_t)E_BONDS * HID];
__device__ float g_msgB  [(size_t)E_BONDS * HID];
__device__ float g_atomh [(size_t)NATOMS  * HID];

// ---- packed f32x2 helpers (sm_103a) ----
__device__ __forceinline__ unsigned long long pack2(float lo, float hi) {
    unsigned long long r;
    asm("mov.b64 %0, {%1, %2};" : "=l"(r) : "f"(lo), "f"(hi));
    return r;
}
__device__ __forceinline__ void unpack2(unsigned long long v, float& lo, float& hi) {
    asm("mov.b64 {%0, %1}, %2;" : "=f"(lo), "=f"(hi) : "l"(v));
}
__device__ __forceinline__ void ffma2(unsigned long long& d,
                                      unsigned long long a, unsigned long long b) {
    asm("fma.rn.f32x2 %0, %1, %2, %0;" : "+l"(d) : "l"(a), "l"(b));
}

// ---- cache-policy load/store helpers ----
__device__ __forceinline__ unsigned long long mk_evict_last() {
    unsigned long long pol;
    asm("createpolicy.fractional.L2::evict_last.b64 %0, 1.0;" : "=l"(pol));
    return pol;
}
__device__ __forceinline__ float4 ldg_keep(const float* p, unsigned long long pol) {
    float4 v;
    asm("ld.global.nc.L2::cache_hint.v4.f32 {%0,%1,%2,%3}, [%4], %5;"
        : "=f"(v.x), "=f"(v.y), "=f"(v.z), "=f"(v.w) : "l"(p), "l"(pol));
    return v;
}
__device__ __forceinline__ float4 ldg_cs(const float* p) {
    float4 v;
    asm("ld.global.cs.v4.f32 {%0,%1,%2,%3}, [%4];"
        : "=f"(v.x), "=f"(v.y), "=f"(v.z), "=f"(v.w) : "l"(p));
    return v;
}
__device__ __forceinline__ int ldg_cs_i(const int* p) {
    int v;
    asm("ld.global.cs.s32 %0, [%1];" : "=r"(v) : "l"(p));
    return v;
}
__device__ __forceinline__ void stg_cs(float* p, float4 v) {
    asm("st.global.cs.v4.f32 [%0], {%1,%2,%3,%4};"
        :: "l"(p), "f"(v.x), "f"(v.y), "f"(v.z), "f"(v.w) : "memory");
}

// ============================================================
// Kernel 1: binput = fbonds @ W_i ; msgA = relu(binput)
// ============================================================
__global__ __launch_bounds__(256)
void k_binput(const float* __restrict__ fbonds,
              const float* __restrict__ W_i)
{
    __shared__ float Wsh[BFD * HID];
    int t = threadIdx.x;
    for (int i = t; i < BFD * HID; i += 256) Wsh[i] = W_i[i];
    __syncthreads();

    int c4 = t & 31, w = t >> 5;
    int gw = blockIdx.x * 8 + w;
    const int nwarps = gridDim.x * 8;

    for (int row = gw; row < E_BONDS; row += nwarps) {
        const float* fr = fbonds + (size_t)row * BFD;
        float4 acc = make_float4(0.f, 0.f, 0.f, 0.f);
        #pragma unroll
        for (int k = 0; k < BFD; k++) {
            float f = __ldg(fr + k);
            float4 wv = *(const float4*)&Wsh[k * HID + c4 * 4];
            acc.x += f * wv.x; acc.y += f * wv.y;
            acc.z += f * wv.z; acc.w += f * wv.w;
        }
        size_t o = (size_t)row * HID + c4 * 4;
        *(float4*)&g_binput[o] = acc;
        float4 rr;
        rr.x = fmaxf(acc.x, 0.f); rr.y = fmaxf(acc.y, 0.f);
        rr.z = fmaxf(acc.z, 0.f); rr.w = fmaxf(acc.w, 0.f);
        *(float4*)&g_msgA[o] = rr;
    }
}

// ============================================================
// Kernel 2: message pass. 32-row tiles, 256 thr, 2 blk/SM.
// Gather: warp wg -> rows 4wg..4wg+3, lane -> 16B col slice,
//         STS.128 into nei[32][NEI_S] (row-major, conflict-free).
// GEMM:   warp wg -> cols 16wg..16wg+15 (all 32 rows);
//         lane (rg = ln&7, cg = ln>>3) -> rows {rg+8i} x cols {4cg..}.
//         Per k: 1 LDS.128 W (8-way bcast, 1 wf) per warp,
//                1 LDS.128 nei (4-way bcast, 1 wf) per 4k per row.
// smem: Wsh 64KB + nei 16.9KB + idx 2KB = 83KB
// ============================================================
__global__ __launch_bounds__(256, 2)
void k_msgpass(const int* __restrict__ bgraph,
               const float* __restrict__ W_h,
               int flag)  // 0: A->B, 1: B->A
{
    extern __shared__ float smem[];
    float* Wsh = smem;                        // [128][128]
    float* nei = smem + HID * HID;            // [32][NEI_S]
    int*   idx = (int*)(nei + 32 * NEI_S);    // [32][16]

    const float* __restrict__ msg_in  = flag ? g_msgB : g_msgA;
    float*       __restrict__ msg_out = flag ? g_msgA : g_msgB;

    const int t   = threadIdx.x;
    const int ln  = t & 31;
    const int wg  = t >> 5;
    const int rg  = ln & 7;        // row group (rows rg, rg+8, rg+16, rg+24)
    const int cg  = ln >> 3;       // col group within warp
    const int wcb = wg * 16;       // warp col base
    const unsigned long long pol = mk_evict_last();

    for (int i = t; i < (HID * HID) / 4; i += 256)
        ((float4*)Wsh)[i] = ((const float4*)W_h)[i];
    __syncthreads();

    const int ntiles = E_BONDS / 32;   // 6250
    for (int tile = blockIdx.x; tile < ntiles; tile += gridDim.x) {
        const int base = tile * 32;

        // stage neighbor indices (streaming)
        for (int i = t; i < 32 * MAX_NB; i += 256) {
            int r = i / MAX_NB, nb = i - r * MAX_NB;
            idx[r * 16 + nb] = ldg_cs_i(bgraph + (size_t)(base + r) * MAX_NB + nb);
        }
        __syncthreads();

        // gather-sum (msg_in kept L2-resident via evict_last)
        #pragma unroll
        for (int i = 0; i < 4; i++) {
            int r = wg * 4 + i;
            float4 s = make_float4(0.f, 0.f, 0.f, 0.f);
            #pragma unroll
            for (int nb = 0; nb < MAX_NB; nb++) {
                int e = idx[r * 16 + nb];
                float4 v = ldg_keep(msg_in + (size_t)e * HID + ln * 4, pol);
                s.x += v.x; s.y += v.y; s.z += v.z; s.w += v.w;
            }
            *(float4*)&nei[r * NEI_S + ln * 4] = s;
        }
        __syncthreads();

        // GEMM + bias + relu
        {
            unsigned long long acc[4][2];
            #pragma unroll
            for (int i = 0; i < 4; i++) {
                float4 b = ldg_cs(&g_binput[(size_t)(base + rg + 8 * i) * HID + wcb + cg * 4]);
                acc[i][0] = pack2(b.x, b.y);
                acc[i][1] = pack2(b.z, b.w);
            }
            #pragma unroll 2
            for (int k0 = 0; k0 < HID; k0 += 4) {
                float4 n0 = *(const float4*)&nei[(rg +  0) * NEI_S + k0];
                float4 n1 = *(const float4*)&nei[(rg +  8) * NEI_S + k0];
                float4 n2 = *(const float4*)&nei[(rg + 16) * NEI_S + k0];
                float4 n3 = *(const float4*)&nei[(rg + 24) * NEI_S + k0];
                #pragma unroll
                for (int j = 0; j < 4; j++) {
                    ulonglong2 w = *(const ulonglong2*)&Wsh[(k0 + j) * HID + wcb + cg * 4];
                    float f0 = ((const float*)&n0)[j];
                    float f1 = ((const float*)&n1)[j];
                    float f2 = ((const float*)&n2)[j];
                    float f3 = ((const float*)&n3)[j];
                    unsigned long long p;
                    p = pack2(f0, f0); ffma2(acc[0][0], p, w.x); ffma2(acc[0][1], p, w.y);
                    p = pack2(f1, f1); ffma2(acc[1][0], p, w.x); ffma2(acc[1][1], p, w.y);
                    p = pack2(f2, f2); ffma2(acc[2][0], p, w.x); ffma2(acc[2][1], p, w.y);
                    p = pack2(f3, f3); ffma2(acc[3][0], p, w.x); ffma2(acc[3][1], p, w.y);
                }
            }
            #pragma unroll
            for (int i = 0; i < 4; i++) {
                float4 o;
                unpack2(acc[i][0], o.x, o.y);
                unpack2(acc[i][1], o.z, o.w);
                o.x = fmaxf(o.x, 0.f); o.y = fmaxf(o.y, 0.f);
                o.z = fmaxf(o.z, 0.f); o.w = fmaxf(o.w, 0.f);
                stg_cs(&msg_out[(size_t)(base + rg + 8 * i) * HID + wcb + cg * 4], o);
            }
        }
        __syncthreads();
    }
}

// ============================================================
// Kernel 3: atom readout. Same 2D warp tiling, K = 148 (padded).
// K-space PERMUTED so gather lands on cols 0..127 (16B-aligned):
//   Wsh row k = W_o row (18+k) for k<128; W_o row (k-128) for
//   128<=k<146; zeros for k=146,147. ain mirrors this layout.
// ============================================================
__global__ __launch_bounds__(256, 2)
void k_atomh(const float* __restrict__ fatoms,
             const int*   __restrict__ agraph,
             const float* __restrict__ W_o,
             const float* __restrict__ b_o)
{
    extern __shared__ float smem[];
    float* Wsh = smem;                        // [148][128]
    float* ain = smem + AINP * HID;           // [32][AINP]
    int*   idx = (int*)(ain + 32 * AINP);     // [32][16]
    __shared__ float bsh[HID];

    const int t   = threadIdx.x;
    const int ln  = t & 31;
    const int wg  = t >> 5;
    const int rg  = ln & 7;
    const int cg  = ln >> 3;
    const int wcb = wg * 16;
    const unsigned long long pol = mk_evict_last();

    // permuted W load
    for (int i = t; i < (AINP * HID) / 4; i += 256) {
        int k = i >> 5;              // /(HID/4)
        int c = (i & 31) * 4;
        float4 v;
        if (k < 128)        v = *(const float4*)&W_o[(size_t)(18 + k) * HID + c];
        else if (k < AIN)   v = *(const float4*)&W_o[(size_t)(k - 128) * HID + c];
        else                v = make_float4(0.f, 0.f, 0.f, 0.f);
        ((float4*)Wsh)[i] = v;
    }
    if (t < HID) bsh[t] = b_o[t];
    __syncthreads();

    const int ntiles = NATOMS / 32;   // 3125
    for (int tile = blockIdx.x; tile < ntiles; tile += gridDim.x) {
        const int base = tile * 32;

        for (int i = t; i < 32 * MAX_NB; i += 256) {
            int r = i / MAX_NB, nb = i - r * MAX_NB;
            idx[r * 16 + nb] = ldg_cs_i(agraph + (size_t)(base + r) * MAX_NB + nb);
        }
        // fatoms -> ain cols 128..145; zero cols 146..147
        for (int i = t; i < 32 * AFD; i += 256) {
            int r = i / AFD, k = i - r * AFD;
            ain[r * AINP + 128 + k] = __ldg(fatoms + (size_t)(base + r) * AFD + k);
        }
        if (t < 64) {
            int r = t >> 1;
            ain[r * AINP + AIN + (t & 1)] = 0.f;
        }
        __syncthreads();

        // gather -> ain cols 0..127
        #pragma unroll
        for (int i = 0; i < 4; i++) {
            int r = wg * 4 + i;
            float4 s = make_float4(0.f, 0.f, 0.f, 0.f);
            #pragma unroll
            for (int nb = 0; nb < MAX_NB; nb++) {
                int e = idx[r * 16 + nb];
                float4 v = ldg_keep(g_msgB + (size_t)e * HID + ln * 4, pol);
                s.x += v.x; s.y += v.y; s.z += v.z; s.w += v.w;
            }
            *(float4*)&ain[r * AINP + ln * 4] = s;
        }
        __syncthreads();

        {
            unsigned long long acc[4][2];
            unsigned long long b01 = pack2(bsh[wcb + cg * 4 + 0], bsh[wcb + cg * 4 + 1]);
            unsigned long long b23 = pack2(bsh[wcb + cg * 4 + 2], bsh[wcb + cg * 4 + 3]);
            #pragma unroll
            for (int i = 0; i < 4; i++) { acc[i][0] = b01; acc[i][1] = b23; }
            #pragma unroll 2
            for (int k0 = 0; k0 < AINP; k0 += 4) {
                float4 n0 = *(const float4*)&ain[(rg +  0) * AINP + k0];
                float4 n1 = *(const float4*)&ain[(rg +  8) * AINP + k0];
                float4 n2 = *(const float4*)&ain[(rg + 16) * AINP + k0];
                float4 n3 = *(const float4*)&ain[(rg + 24) * AINP + k0];
                #pragma unroll
                for (int j = 0; j < 4; j++) {
                    ulonglong2 w = *(const ulonglong2*)&Wsh[(k0 + j) * HID + wcb + cg * 4];
                    float f0 = ((const float*)&n0)[j];
                    float f1 = ((const float*)&n1)[j];
                    float f2 = ((const float*)&n2)[j];
                    float f3 = ((const float*)&n3)[j];
                    unsigned long long p;
                    p = pack2(f0, f0); ffma2(acc[0][0], p, w.x); ffma2(acc[0][1], p, w.y);
                    p = pack2(f1, f1); ffma2(acc[1][0], p, w.x); ffma2(acc[1][1], p, w.y);
                    p = pack2(f2, f2); ffma2(acc[2][0], p, w.x); ffma2(acc[2][1], p, w.y);
                    p = pack2(f3, f3); ffma2(acc[3][0], p, w.x); ffma2(acc[3][1], p, w.y);
                }
            }
            #pragma unroll
            for (int i = 0; i < 4; i++) {
                float4 o;
                unpack2(acc[i][0], o.x, o.y);
                unpack2(acc[i][1], o.z, o.w);
                o.x = fmaxf(o.x, 0.f); o.y = fmaxf(o.y, 0.f);
                o.z = fmaxf(o.z, 0.f); o.w = fmaxf(o.w, 0.f);
                *(float4*)&g_atomh[(size_t)(base + rg + 8 * i) * HID + wcb + cg * 4] = o;
            }
        }
        __syncthreads();
    }
}

// ============================================================
// Kernel 4: segment mean pooling.
// ============================================================
__global__ void k_pool(const int* __restrict__ scope_start,
                       const int* __restrict__ scope_len,
                       float* __restrict__ out)
{
    int m = blockIdx.x, t = threadIdx.x; // 128 threads
    int s = scope_start[m], L = scope_len[m];
    float acc = 0.f;
    for (int i = 0; i < L; i++)
        acc += g_atomh[(size_t)(s + i) * HID + t];
    out[(size_t)m * HID + t] = acc / (float)L;
}

// ============================================================
extern "C" void kernel_launch(void* const* d_in, const int* in_sizes, int n_in,
                              void* d_out, int out_size)
{
    const float* fatoms      = (const float*)d_in[0];
    const float* fbonds      = (const float*)d_in[1];
    const int*   agraph      = (const int*)  d_in[2];
    const int*   bgraph      = (const int*)  d_in[3];
    const int*   scope_start = (const int*)  d_in[4];
    const int*   scope_len   = (const int*)  d_in[5];
    const float* W_i         = (const float*)d_in[6];
    const float* W_h         = (const float*)d_in[7];
    const float* W_o         = (const float*)d_in[8];
    const float* b_o         = (const float*)d_in[9];
    float* out = (float*)d_out;

    const int SMEM2 = (HID * HID + 32 * NEI_S + 32 * 16) * 4;   // 84480
    const int SMEM3 = (AINP * HID + 32 * AINP + 32 * 16) * 4;   // 96768

    cudaFuncSetAttribute(k_msgpass, cudaFuncAttributeMaxDynamicSharedMemorySize, SMEM2);
    cudaFuncSetAttribute(k_atomh,   cudaFuncAttributeMaxDynamicSharedMemorySize, SMEM3);

    k_binput<<<1024, 256>>>(fbonds, W_i);

    for (int d = 0; d < NPASS; d++)
        k_msgpass<<<296, 256, SMEM2>>>(bgraph, W_h, d & 1);

    k_atomh<<<296, 256, SMEM3>>>(fatoms, agraph, W_o, b_o);

    k_pool<<<NMOLS, 128>>>(scope_start, scope_len, out);
}

// round 5
// speedup vs baseline: 1.1338x; 1.0233x over previous
#include <cuda_runtime.h>
#include <cstddef>
#include <cstdint>

#define E_BONDS   200000
#define NATOMS    100000
#define HID       128
#define MAX_NB    15
#define BFD       23      // ATOM_FDIM + BOND_FDIM
#define AFD       18      // ATOM_FDIM
#define AIN       146     // AFD + HID
#define AINP      148     // padded K for atomh
#define NMOLS     2000
#define NPASS     5       // DEPTH - 1

#define NEI_S     132     // nei row stride (floats): 16B-aligned; consecutive rows
                          // 4 banks apart -> conflict-free strided LDS.128

// ---- scratch (device globals: alloc-free, graph-capturable) ----
__device__ float g_binput[(size_t)E_BONDS * HID];
__device__ float g_msgA  [(size_t)E_BONDS * HID];
__device__ float g_msgB  [(size_t)E_BONDS * HID];
__device__ float g_atomh [(size_t)NATOMS  * HID];

// ---- packed f32x2 helpers (sm_103a) ----
__device__ __forceinline__ unsigned long long pack2(float lo, float hi) {
    unsigned long long r;
    asm("mov.b64 %0, {%1, %2};" : "=l"(r) : "f"(lo), "f"(hi));
    return r;
}
__device__ __forceinline__ void unpack2(unsigned long long v, float& lo, float& hi) {
    asm("mov.b64 {%0, %1}, %2;" : "=f"(lo), "=f"(hi) : "l"(v));
}
__device__ __forceinline__ void ffma2(unsigned long long& d,
                                      unsigned long long a, unsigned long long b) {
    asm("fma.rn.f32x2 %0, %1, %2, %0;" : "+l"(d) : "l"(a), "l"(b));
}
__device__ __forceinline__ void fadd2(unsigned long long& d, unsigned long long a) {
    asm("add.rn.f32x2 %0, %0, %1;" : "+l"(d) : "l"(a));
}

// ---- cache-policy load helpers ----
__device__ __forceinline__ unsigned long long mk_evict_last() {
    unsigned long long pol;
    asm("createpolicy.fractional.L2::evict_last.b64 %0, 1.0;" : "=l"(pol));
    return pol;
}
__device__ __forceinline__ float4 ldg_keep(const float* p, unsigned long long pol) {
    float4 v;
    asm("ld.global.nc.L2::cache_hint.v4.f32 {%0,%1,%2,%3}, [%4], %5;"
        : "=f"(v.x), "=f"(v.y), "=f"(v.z), "=f"(v.w) : "l"(p), "l"(pol));
    return v;
}
__device__ __forceinline__ float4 ldg_cs(const float* p) {
    float4 v;
    asm("ld.global.cs.v4.f32 {%0,%1,%2,%3}, [%4];"
        : "=f"(v.x), "=f"(v.y), "=f"(v.z), "=f"(v.w) : "l"(p));
    return v;
}
__device__ __forceinline__ int ldg_cs_i(const int* p) {
    int v;
    asm("ld.global.cs.s32 %0, [%1];" : "=r"(v) : "l"(p));
    return v;
}
__device__ __forceinline__ void stg_cs(float* p, float4 v) {
    asm("st.global.cs.v4.f32 [%0], {%1,%2,%3,%4};"
        :: "l"(p), "f"(v.x), "f"(v.y), "f"(v.z), "f"(v.w) : "memory");
}

// ============================================================
// Kernel 1: binput = fbonds @ W_i ; msgA = relu(binput)
// ============================================================
__global__ __launch_bounds__(256)
void k_binput(const float* __restrict__ fbonds,
              const float* __restrict__ W_i)
{
    __shared__ float Wsh[BFD * HID];
    int t = threadIdx.x;
    for (int i = t; i < BFD * HID; i += 256) Wsh[i] = W_i[i];
    __syncthreads();

    int c4 = t & 31, w = t >> 5;
    int gw = blockIdx.x * 8 + w;
    const int nwarps = gridDim.x * 8;

    for (int row = gw; row < E_BONDS; row += nwarps) {
        const float* fr = fbonds + (size_t)row * BFD;
        float4 acc = make_float4(0.f, 0.f, 0.f, 0.f);
        #pragma unroll
        for (int k = 0; k < BFD; k++) {
            float f = __ldg(fr + k);
            float4 wv = *(const float4*)&Wsh[k * HID + c4 * 4];
            acc.x += f * wv.x; acc.y += f * wv.y;
            acc.z += f * wv.z; acc.w += f * wv.w;
        }
        size_t o = (size_t)row * HID + c4 * 4;
        *(float4*)&g_binput[o] = acc;
        float4 rr;
        rr.x = fmaxf(acc.x, 0.f); rr.y = fmaxf(acc.y, 0.f);
        rr.z = fmaxf(acc.z, 0.f); rr.w = fmaxf(acc.w, 0.f);
        *(float4*)&g_msgA[o] = rr;
    }
}

// ============================================================
// warp-local gather of 4 rows of one tile into a nei buffer.
// idx via 1 coalesced LDG + shfl (no smem, no extra barrier).
// ============================================================
__device__ __forceinline__ void gather4(const float* __restrict__ msg_in,
                                        const int*   __restrict__ graph,
                                        int base, int wg, int ln,
                                        float* __restrict__ buf, int stride,
                                        unsigned long long pol)
{
    #pragma unroll
    for (int i = 0; i < 4; i++) {
        int r = wg * 4 + i;
        int e0 = 0;
        if (ln < MAX_NB)
            e0 = ldg_cs_i(graph + (size_t)(base + r) * MAX_NB + ln);
        float4 s = make_float4(0.f, 0.f, 0.f, 0.f);
        #pragma unroll
        for (int nb = 0; nb < MAX_NB; nb++) {
            int e = __shfl_sync(0xffffffffu, e0, nb);
            float4 v = ldg_keep(msg_in + (size_t)e * HID + ln * 4, pol);
            s.x += v.x; s.y += v.y; s.z += v.z; s.w += v.w;
        }
        *(float4*)&buf[r * stride + ln * 4] = s;
    }
}

// ============================================================
// Kernel 2: message pass, software-pipelined.
//   per iter: sync; gather(t+G) -> nei[next]; GEMM(t) from nei[cur]
// GEMM: warp wg -> cols 16wg..16wg+15, lane (rg=ln&7,cg=ln>>3) ->
//   rows {rg+8i} x cols {4cg..}; acc zero-init, binput added at end.
// smem: Wsh 64KB + 2*nei 33KB = 97KB -> 2 blk/SM
// ============================================================
__global__ __launch_bounds__(256, 2)
void k_msgpass(const int* __restrict__ bgraph,
               const float* __restrict__ W_h,
               int flag)  // 0: A->B, 1: B->A
{
    extern __shared__ float smem[];
    float* Wsh  = smem;                       // [128][128]
    float* neiD = smem + HID * HID;           // 2 x [32][NEI_S]

    const float* __restrict__ msg_in  = flag ? g_msgB : g_msgA;
    float*       __restrict__ msg_out = flag ? g_msgA : g_msgB;

    const int t   = threadIdx.x;
    const int ln  = t & 31;
    const int wg  = t >> 5;
    const int rg  = ln & 7;
    const int cg  = ln >> 3;
    const int wcb = wg * 16;
    const unsigned long long pol = mk_evict_last();

    for (int i = t; i < (HID * HID) / 4; i += 256)
        ((float4*)Wsh)[i] = ((const float4*)W_h)[i];

    const int ntiles = E_BONDS / 32;   // 6250
    int tile = blockIdx.x;
    int cur  = 0;

    if (tile < ntiles)
        gather4(msg_in, bgraph, tile * 32, wg, ln, neiD, NEI_S, pol);

    for (; tile < ntiles; tile += gridDim.x) {
        __syncthreads();   // nei[cur] (and W on first iter) ready

        int nxt = tile + gridDim.x;
        if (nxt < ntiles)
            gather4(msg_in, bgraph, nxt * 32, wg, ln,
                    neiD + (cur ^ 1) * 32 * NEI_S, NEI_S, pol);

        // ---- GEMM(tile) from nei[cur] ----
        const float* nei = neiD + cur * 32 * NEI_S;
        const int base = tile * 32;

        // issue binput loads early; consumed only at epilogue
        float4 bin[4];
        #pragma unroll
        for (int i = 0; i < 4; i++)
            bin[i] = ldg_cs(&g_binput[(size_t)(base + rg + 8 * i) * HID + wcb + cg * 4]);

        unsigned long long acc[4][2];
        #pragma unroll
        for (int i = 0; i < 4; i++) { acc[i][0] = 0ull; acc[i][1] = 0ull; }

        #pragma unroll 2
        for (int k0 = 0; k0 < HID; k0 += 4) {
            float4 n0 = *(const float4*)&nei[(rg +  0) * NEI_S + k0];
            float4 n1 = *(const float4*)&nei[(rg +  8) * NEI_S + k0];
            float4 n2 = *(const float4*)&nei[(rg + 16) * NEI_S + k0];
            float4 n3 = *(const float4*)&nei[(rg + 24) * NEI_S + k0];
            #pragma unroll
            for (int j = 0; j < 4; j++) {
                ulonglong2 w = *(const ulonglong2*)&Wsh[(k0 + j) * HID + wcb + cg * 4];
                float f0 = ((const float*)&n0)[j];
                float f1 = ((const float*)&n1)[j];
                float f2 = ((const float*)&n2)[j];
                float f3 = ((const float*)&n3)[j];
                unsigned long long p;
                p = pack2(f0, f0); ffma2(acc[0][0], p, w.x); ffma2(acc[0][1], p, w.y);
                p = pack2(f1, f1); ffma2(acc[1][0], p, w.x); ffma2(acc[1][1], p, w.y);
                p = pack2(f2, f2); ffma2(acc[2][0], p, w.x); ffma2(acc[2][1], p, w.y);
                p = pack2(f3, f3); ffma2(acc[3][0], p, w.x); ffma2(acc[3][1], p, w.y);
            }
        }
        #pragma unroll
        for (int i = 0; i < 4; i++) {
            fadd2(acc[i][0], pack2(bin[i].x, bin[i].y));
            fadd2(acc[i][1], pack2(bin[i].z, bin[i].w));
            float4 o;
            unpack2(acc[i][0], o.x, o.y);
            unpack2(acc[i][1], o.z, o.w);
            o.x = fmaxf(o.x, 0.f); o.y = fmaxf(o.y, 0.f);
            o.z = fmaxf(o.z, 0.f); o.w = fmaxf(o.w, 0.f);
            stg_cs(&msg_out[(size_t)(base + rg + 8 * i) * HID + wcb + cg * 4], o);
        }
        cur ^= 1;
    }
}

// ============================================================
// Kernel 3: atom readout, same pipelined template. K = 148.
// K-permuted: gather -> cols 0..127 (16B aligned), fatoms -> 128..145,
// zeros -> 146..147; Wsh rows permuted to match.
// smem: Wsh 74KB + 2*ain[32][148] 37KB = 111KB -> 2 blk/SM
// ============================================================
__global__ __launch_bounds__(256, 2)
void k_atomh(const float* __restrict__ fatoms,
             const int*   __restrict__ agraph,
             const float* __restrict__ W_o,
             const float* __restrict__ b_o)
{
    extern __shared__ float smem[];
    float* Wsh  = smem;                       // [148][128]
    float* ainD = smem + AINP * HID;          // 2 x [32][AINP]
    __shared__ float bsh[HID];

    const int t   = threadIdx.x;
    const int ln  = t & 31;
    const int wg  = t >> 5;
    const int rg  = ln & 7;
    const int cg  = ln >> 3;
    const int wcb = wg * 16;
    const unsigned long long pol = mk_evict_last();

    for (int i = t; i < (AINP * HID) / 4; i += 256) {
        int k = i >> 5;
        int c = (i & 31) * 4;
        float4 v;
        if (k < 128)      v = *(const float4*)&W_o[(size_t)(AFD + k) * HID + c];
        else if (k < AIN) v = *(const float4*)&W_o[(size_t)(k - 128) * HID + c];
        else              v = make_float4(0.f, 0.f, 0.f, 0.f);
        ((float4*)Wsh)[i] = v;
    }
    if (t < HID) bsh[t] = b_o[t];

    const int ntiles = NATOMS / 32;   // 3125
    int tile = blockIdx.x;
    int cur  = 0;

    // warp-local fill of one tile's ain buffer
    auto fill = [&](int tl, float* buf) {
        const int base = tl * 32;
        gather4(g_msgB, agraph, base, wg, ln, buf, AINP, pol);
        #pragma unroll
        for (int i = 0; i < 4; i++) {
            int r = wg * 4 + i;
            if (ln < AFD)
                buf[r * AINP + 128 + ln] = __ldg(fatoms + (size_t)(base + r) * AFD + ln);
            else if (ln < 20)
                buf[r * AINP + 128 + ln] = 0.f;
        }
    };

    if (tile < ntiles) fill(tile, ainD);

    for (; tile < ntiles; tile += gridDim.x) {
        __syncthreads();

        int nxt = tile + gridDim.x;
        if (nxt < ntiles) fill(nxt, ainD + (cur ^ 1) * 32 * AINP);

        const float* ain = ainD + cur * 32 * AINP;
        const int base = tile * 32;

        unsigned long long acc[4][2];
        #pragma unroll
        for (int i = 0; i < 4; i++) { acc[i][0] = 0ull; acc[i][1] = 0ull; }

        #pragma unroll 2
        for (int k0 = 0; k0 < AINP; k0 += 4) {
            float4 n0 = *(const float4*)&ain[(rg +  0) * AINP + k0];
            float4 n1 = *(const float4*)&ain[(rg +  8) * AINP + k0];
            float4 n2 = *(const float4*)&ain[(rg + 16) * AINP + k0];
            float4 n3 = *(const float4*)&ain[(rg + 24) * AINP + k0];
            #pragma unroll
            for (int j = 0; j < 4; j++) {
                ulonglong2 w = *(const ulonglong2*)&Wsh[(k0 + j) * HID + wcb + cg * 4];
                float f0 = ((const float*)&n0)[j];
                float f1 = ((const float*)&n1)[j];
                float f2 = ((const float*)&n2)[j];
                float f3 = ((const float*)&n3)[j];
                unsigned long long p;
                p = pack2(f0, f0); ffma2(acc[0][0], p, w.x); ffma2(acc[0][1], p, w.y);
                p = pack2(f1, f1); ffma2(acc[1][0], p, w.x); ffma2(acc[1][1], p, w.y);
                p = pack2(f2, f2); ffma2(acc[2][0], p, w.x); ffma2(acc[2][1], p, w.y);
                p = pack2(f3, f3); ffma2(acc[3][0], p, w.x); ffma2(acc[3][1], p, w.y);
            }
        }
        unsigned long long b01 = pack2(bsh[wcb + cg * 4 + 0], bsh[wcb + cg * 4 + 1]);
        unsigned long long b23 = pack2(bsh[wcb + cg * 4 + 2], bsh[wcb + cg * 4 + 3]);
        #pragma unroll
        for (int i = 0; i < 4; i++) {
            fadd2(acc[i][0], b01);
            fadd2(acc[i][1], b23);
            float4 o;
            unpack2(acc[i][0], o.x, o.y);
            unpack2(acc[i][1], o.z, o.w);
            o.x = fmaxf(o.x, 0.f); o.y = fmaxf(o.y, 0.f);
            o.z = fmaxf(o.z, 0.f); o.w = fmaxf(o.w, 0.f);
            *(float4*)&g_atomh[(size_t)(base + rg + 8 * i) * HID + wcb + cg * 4] = o;
        }
        cur ^= 1;
    }
}

// ============================================================
// Kernel 4: segment mean pooling.
// ============================================================
__global__ void k_pool(const int* __restrict__ scope_start,
                       const int* __restrict__ scope_len,
                       float* __restrict__ out)
{
    int m = blockIdx.x, t = threadIdx.x; // 128 threads
    int s = scope_start[m], L = scope_len[m];
    float acc = 0.f;
    for (int i = 0; i < L; i++)
        acc += g_atomh[(size_t)(s + i) * HID + t];
    out[(size_t)m * HID + t] = acc / (float)L;
}

// ============================================================
extern "C" void kernel_launch(void* const* d_in, const int* in_sizes, int n_in,
                              void* d_out, int out_size)
{
    const float* fatoms      = (const float*)d_in[0];
    const float* fbonds      = (const float*)d_in[1];
    const int*   agraph      = (const int*)  d_in[2];
    const int*   bgraph      = (const int*)  d_in[3];
    const int*   scope_start = (const int*)  d_in[4];
    const int*   scope_len   = (const int*)  d_in[5];
    const float* W_i         = (const float*)d_in[6];
    const float* W_h         = (const float*)d_in[7];
    const float* W_o         = (const float*)d_in[8];
    const float* b_o         = (const float*)d_in[9];
    float* out = (float*)d_out;

    const int SMEM2 = (HID * HID + 2 * 32 * NEI_S) * 4;    // 99328
    const int SMEM3 = (AINP * HID + 2 * 32 * AINP) * 4;    // 113664

    cudaFuncSetAttribute(k_msgpass, cudaFuncAttributeMaxDynamicSharedMemorySize, SMEM2);
    cudaFuncSetAttribute(k_atomh,   cudaFuncAttributeMaxDynamicSharedMemorySize, SMEM3);

    k_binput<<<1024, 256>>>(fbonds, W_i);

    for (int d = 0; d < NPASS; d++)
        k_msgpass<<<296, 256, SMEM2>>>(bgraph, W_h, d & 1);

    k_atomh<<<296, 256, SMEM3>>>(fatoms, agraph, W_o, b_o);

    k_pool<<<NMOLS, 128>>>(scope_start, scope_len, out);
}